// round 3
// baseline (speedup 1.0000x reference)
#include <cuda_runtime.h>

// Model_PDE_2: N=131072 points, H=1024 hidden tanh units, D=2.
// f32x2-packed version: each thread processes ONE PAIR of consecutive points,
// all per-h math done with packed fma.rn.f32x2 (Blackwell FFMA2).
//
//   t   = tanh(x0*a_h + x1*b_h + c_h)
//   out = sum_h t*w_h + b2
//   g0  = C0 - sum_h t^2 * (w*a)_h        (df_dt)   C0 = sum wa
//   g1  = C1 - sum_h t^2 * (w*b)_h        (df_dx)   C1 = sum wb
//   dxdx= sum_h (t - t^3) * (-2*w*b^2)_h  = P - Q, twin accumulators
//   pde = 0.5*x1^2 + g0 + 0.5*dxdx + 0.5*x1*g1 - (0.25/3.6)*g1^2
// Output: d_out[0..N) = out, d_out[N..2N) = pde.

#define HID 1024
#define TPB 256

typedef unsigned long long u64;

// Weights duplicated into (v,v) 64-bit pairs, 8 slots of 8B per h = 64B/h:
// slot 0:{a,a} 1:{b,b} 2:{c,c} 3:{w,w} 4:{wa,wa} 5:{wb,wb} 6:{wbb,wbb} 7:pad
__device__ float g_w16[HID * 16];
__device__ float g_c01[2];

__global__ void setup_kernel(const float* __restrict__ W1,
                             const float* __restrict__ b1,
                             const float* __restrict__ w2) {
    __shared__ float redA[HID];
    __shared__ float redB[HID];
    int h = threadIdx.x;
    float a = W1[2 * h], b = W1[2 * h + 1];
    float c = b1[h], w = w2[h];
    float wa = w * a;
    float wb = w * b;
    float wbb = -2.0f * w * b * b;
    float* p = &g_w16[16 * h];
    p[0] = a;   p[1] = a;
    p[2] = b;   p[3] = b;
    p[4] = c;   p[5] = c;
    p[6] = w;   p[7] = w;
    p[8] = wa;  p[9] = wa;
    p[10] = wb; p[11] = wb;
    p[12] = wbb; p[13] = wbb;
    p[14] = 0.0f; p[15] = 0.0f;
    redA[h] = wa;
    redB[h] = wb;
    __syncthreads();
    for (int s = HID / 2; s > 0; s >>= 1) {
        if (h < s) {
            redA[h] += redA[h + s];
            redB[h] += redB[h + s];
        }
        __syncthreads();
    }
    if (h == 0) {
        g_c01[0] = redA[0];
        g_c01[1] = redB[0];
    }
}

__device__ __forceinline__ float tanh_fast(float z) {
    float t;
    asm("tanh.approx.f32 %0, %1;" : "=f"(t) : "f"(z));
    return t;
}
__device__ __forceinline__ u64 fma2(u64 a, u64 b, u64 c) {
    u64 d;
    asm("fma.rn.f32x2 %0, %1, %2, %3;" : "=l"(d) : "l"(a), "l"(b), "l"(c));
    return d;
}
__device__ __forceinline__ u64 mul2(u64 a, u64 b) {
    u64 d;
    asm("mul.rn.f32x2 %0, %1, %2;" : "=l"(d) : "l"(a), "l"(b));
    return d;
}
__device__ __forceinline__ u64 pk(float lo, float hi) {
    u64 r;
    asm("mov.b64 %0, {%1, %2};" : "=l"(r) : "f"(lo), "f"(hi));
    return r;
}
__device__ __forceinline__ void upk(u64 v, float& lo, float& hi) {
    asm("mov.b64 {%0, %1}, %2;" : "=f"(lo), "=f"(hi) : "l"(v));
}

__global__ __launch_bounds__(TPB) void pde_kernel(const float* __restrict__ x,
                                                  const float* __restrict__ b2,
                                                  float* __restrict__ out,
                                                  int N) {
    extern __shared__ ulonglong2 sw[];  // 64 KB: 4 x 16B per h

    const ulonglong2* gp = reinterpret_cast<const ulonglong2*>(g_w16);
    for (int i = threadIdx.x; i < HID * 4; i += TPB) sw[i] = gp[i];
    __syncthreads();

    // Thread owns pair index p -> points 2p, 2p+1 (coalesced float4 load).
    int p = blockIdx.x * TPB + threadIdx.x;
    int npairs = N >> 1;
    if (p >= npairs) return;

    float4 xv = reinterpret_cast<const float4*>(x)[p];
    u64 px0 = pk(xv.x, xv.z);  // x0 of both points
    u64 px1 = pk(xv.y, xv.w);  // x1 of both points

    u64 acc_out = 0ULL;  // (0.0f, 0.0f)
    u64 acc_gA = 0ULL;
    u64 acc_gB = 0ULL;
    u64 acc_dxP = 0ULL;
    u64 acc_dxQ = 0ULL;

#pragma unroll 8
    for (int h = 0; h < HID; h++) {
        ulonglong2 q0 = sw[4 * h];      // {aa, bb}
        ulonglong2 q1 = sw[4 * h + 1];  // {cc, ww}
        ulonglong2 q2 = sw[4 * h + 2];  // {waa, wbb}
        ulonglong2 q3 = sw[4 * h + 3];  // {wbbbb, pad}

        u64 z = fma2(px0, q0.x, q1.x);
        z = fma2(px1, q0.y, z);

        float zl, zh;
        upk(z, zl, zh);
        u64 t = pk(tanh_fast(zl), tanh_fast(zh));

        u64 tt = mul2(t, t);
        acc_out = fma2(t, q1.y, acc_out);
        acc_gA = fma2(tt, q2.x, acc_gA);
        acc_gB = fma2(tt, q2.y, acc_gB);
        u64 t3 = mul2(tt, t);
        acc_dxP = fma2(t, q3.x, acc_dxP);   //  sum t   * wbb
        acc_dxQ = fma2(t3, q3.x, acc_dxQ);  //  sum t^3 * wbb
    }

    float C0 = g_c01[0];
    float C1 = g_c01[1];
    float bias2 = b2[0];

    float ao0, ao1, gA0, gA1, gB0, gB1, dP0, dP1, dQ0, dQ1;
    upk(acc_out, ao0, ao1);
    upk(acc_gA, gA0, gA1);
    upk(acc_gB, gB0, gB1);
    upk(acc_dxP, dP0, dP1);
    upk(acc_dxQ, dQ0, dQ1);

    float x1a = xv.y, x1b = xv.w;

    // point 0
    float g0a = C0 - gA0;
    float g1a = C1 - gB0;
    float dxa = dP0 - dQ0;
    float pdea = __fmaf_rn(0.5f * x1a, x1a, g0a);
    pdea = __fmaf_rn(0.5f, dxa, pdea);
    pdea = __fmaf_rn(0.5f * x1a, g1a, pdea);
    pdea = __fmaf_rn(-0.069444444444444444f * g1a, g1a, pdea);

    // point 1
    float g0b = C0 - gA1;
    float g1b = C1 - gB1;
    float dxb = dP1 - dQ1;
    float pdeb = __fmaf_rn(0.5f * x1b, x1b, g0b);
    pdeb = __fmaf_rn(0.5f, dxb, pdeb);
    pdeb = __fmaf_rn(0.5f * x1b, g1b, pdeb);
    pdeb = __fmaf_rn(-0.069444444444444444f * g1b, g1b, pdeb);

    reinterpret_cast<float2*>(out)[p] = make_float2(ao0 + bias2, ao1 + bias2);
    reinterpret_cast<float2*>(out + N)[p] = make_float2(pdea, pdeb);
}

extern "C" void kernel_launch(void* const* d_in, const int* in_sizes, int n_in,
                              void* d_out, int out_size) {
    const float* x = (const float*)d_in[0];
    const float* W1 = (const float*)d_in[1];
    const float* b1 = (const float*)d_in[2];
    const float* w2 = (const float*)d_in[3];
    const float* b2 = (const float*)d_in[4];
    int N = in_sizes[0] / 2;

    static int smem_set = 0;
    // cudaFuncSetAttribute is not a stream operation; safe under graph capture.
    // Called unconditionally (deterministic); static flag only avoids repeat API calls.
    if (!smem_set) {
        cudaFuncSetAttribute(pde_kernel, cudaFuncAttributeMaxDynamicSharedMemorySize,
                             64 * 1024);
        smem_set = 1;
    }

    setup_kernel<<<1, HID>>>(W1, b1, w2);
    int npairs = N / 2;
    int grid = (npairs + TPB - 1) / TPB;
    pde_kernel<<<grid, TPB, 64 * 1024>>>(x, b2, (float*)d_out, N);
}

// round 5
// speedup vs baseline: 1.1626x; 1.1626x over previous
#include <cuda_runtime.h>

// Model_PDE_2: N=131072 points, H=1024 hidden tanh units, D=2.
//   t   = tanh(x0*a_h + x1*b_h + c_h)
//   out = sum_h t*w_h + b2
//   g0  = C0 - sum_h t^2 * (w*a)_h        (df_dt)   C0 = sum wa
//   g1  = C1 - sum_h t^2 * (w*b)_h        (df_dx)   C1 = sum wb
//   dxdx= sum_h (t - t^3) * (-2*w*b^2)_h  (df_dxdx)
//   pde = 0.5*x1^2 + g0 + 0.5*dxdx + 0.5*x1*g1 - (0.25/3.6)*g1^2
// Output layout: d_out[0..N) = out, d_out[N..2N) = pde.
//
// R5: TPB=128, 1 point/thread, grid=1024 (98.9% SM balance), smem cut to
// 28KB/CTA so 7 CTAs (28 warps) fit per SM -> single fully-resident wave.

#define HID 1024
#define TPB 128

__device__ float4 g_t0[HID];  // {a, b, c, w}
__device__ float2 g_t1[HID];  // {wa, wb}
__device__ float g_t2[HID];   // {wbb}
__device__ float g_c01[2];

__global__ void setup_kernel(const float* __restrict__ W1,
                             const float* __restrict__ b1,
                             const float* __restrict__ w2) {
    __shared__ float redA[HID];
    __shared__ float redB[HID];
    int h = threadIdx.x;
    float a = W1[2 * h], b = W1[2 * h + 1];
    float c = b1[h], w = w2[h];
    float wa = w * a;
    float wb = w * b;
    float wbb = -2.0f * w * b * b;
    g_t0[h] = make_float4(a, b, c, w);
    g_t1[h] = make_float2(wa, wb);
    g_t2[h] = wbb;
    redA[h] = wa;
    redB[h] = wb;
    __syncthreads();
    for (int s = HID / 2; s > 0; s >>= 1) {
        if (h < s) {
            redA[h] += redA[h + s];
            redB[h] += redB[h + s];
        }
        __syncthreads();
    }
    if (h == 0) {
        g_c01[0] = redA[0];
        g_c01[1] = redB[0];
    }
}

__device__ __forceinline__ float tanh_fast(float z) {
    float t;
    asm("tanh.approx.f32 %0, %1;" : "=f"(t) : "f"(z));
    return t;
}

__global__ __launch_bounds__(TPB) void pde_kernel(const float* __restrict__ x,
                                                  const float* __restrict__ b2,
                                                  float* __restrict__ out,
                                                  int N) {
    __shared__ float4 s0[HID];  // 16 KB
    __shared__ float2 s1[HID];  // 8 KB
    __shared__ float s2[HID];   // 4 KB

    for (int i = threadIdx.x; i < HID; i += TPB) {
        s0[i] = g_t0[i];
        s1[i] = g_t1[i];
        s2[i] = g_t2[i];
    }
    __syncthreads();

    int n = blockIdx.x * TPB + threadIdx.x;
    if (n >= N) return;

    float2 xv = reinterpret_cast<const float2*>(x)[n];
    float x0 = xv.x, x1 = xv.y;

    float acc_out = 0.0f;
    float acc_gA = 0.0f;
    float acc_gB = 0.0f;
    float acc_dx = 0.0f;

#pragma unroll 8
    for (int h = 0; h < HID; h++) {
        float4 q = s0[h];
        float2 r = s1[h];
        float u = s2[h];
        float z = __fmaf_rn(x1, q.y, __fmaf_rn(x0, q.x, q.z));
        float t = tanh_fast(z);
        float tt = t * t;
        acc_out = __fmaf_rn(t, q.w, acc_out);
        acc_gA = __fmaf_rn(tt, r.x, acc_gA);
        acc_gB = __fmaf_rn(tt, r.y, acc_gB);
        float t3 = __fmaf_rn(-t, tt, t);  // t - t^3
        acc_dx = __fmaf_rn(t3, u, acc_dx);
    }

    float g0 = g_c01[0] - acc_gA;  // df_dt
    float g1 = g_c01[1] - acc_gB;  // df_dx
    float outv = acc_out + b2[0];

    // pde = 0.5*x1^2 + g0 + 0.5*dxdx + 0.5*x1*g1 - (0.25/(4*0.9))*g1^2
    float pde = __fmaf_rn(0.5f * x1, x1, g0);
    pde = __fmaf_rn(0.5f, acc_dx, pde);
    pde = __fmaf_rn(0.5f * x1, g1, pde);
    pde = __fmaf_rn(-0.069444444444444444f * g1, g1, pde);

    out[n] = outv;
    out[N + n] = pde;
}

extern "C" void kernel_launch(void* const* d_in, const int* in_sizes, int n_in,
                              void* d_out, int out_size) {
    const float* x = (const float*)d_in[0];
    const float* W1 = (const float*)d_in[1];
    const float* b1 = (const float*)d_in[2];
    const float* w2 = (const float*)d_in[3];
    const float* b2 = (const float*)d_in[4];
    int N = in_sizes[0] / 2;

    static int inited = 0;
    if (!inited) {
        // Max shared-memory carveout so 7 CTAs (7 x 29KB) fit per SM.
        cudaFuncSetAttribute(pde_kernel,
                             cudaFuncAttributePreferredSharedMemoryCarveout, 100);
        inited = 1;
    }

    setup_kernel<<<1, HID>>>(W1, b1, w2);
    pde_kernel<<<(N + TPB - 1) / TPB, TPB>>>(x, b2, (float*)d_out, N);
}

// round 6
// speedup vs baseline: 1.3731x; 1.1810x over previous
#include <cuda_runtime.h>
#include <cstdint>

// Model_PDE_2: N=131072, H=1024, D=2.
// tf32 mma.sync (sm_80-class) formulation:
//   per (n,h): z = x0*a+x1*b+c; t = tanh(z); values {t, tt=t^2, t3=t-t^3}
//   4 contractions as D[32pts x 8] = A[32 x 3072] * B[3072 x 8]:
//     col n=0: out = sum t*w ; n=1: gA = sum tt*wa ; n=2: gB = sum tt*wb
//     n=3: dx = sum t3*wbb (wbb = -2*w*b^2) ; n=4..7 unused (zero B)
//   K layout: triples of 24 cols, col = j*8 + c -> value_j(h = tri*8 + c)
//   g0 = C0-gA, g1 = C1-gB; pde = .5*x1^2 + g0 + .5*dx + .5*x1*g1 - (.25/3.6)*g1^2
// Output: d_out[0..N)=out, d_out[N..2N)=pde.

#define HID 1024
#define TPB 128
#define NTRI (HID / 8)   // 128 triples of 8 h
#define WT_STRIDE 1032   // 4 pages offset by 8 banks -> conflict-free

__device__ float2 g_ab[HID];   // {a, b}
__device__ float g_cc[HID];    // c
__device__ float4 g_wv[HID];   // {w, wa, wb, wbb}
__device__ float g_c01[2];

__global__ void setup_kernel(const float* __restrict__ W1,
                             const float* __restrict__ b1,
                             const float* __restrict__ w2) {
    __shared__ float redA[HID];
    __shared__ float redB[HID];
    int h = threadIdx.x;
    float a = W1[2 * h], b = W1[2 * h + 1];
    float c = b1[h], w = w2[h];
    float wa = w * a;
    float wb = w * b;
    float wbb = -2.0f * w * b * b;
    g_ab[h] = make_float2(a, b);
    g_cc[h] = c;
    g_wv[h] = make_float4(w, wa, wb, wbb);
    redA[h] = wa;
    redB[h] = wb;
    __syncthreads();
    for (int s = HID / 2; s > 0; s >>= 1) {
        if (h < s) {
            redA[h] += redA[h + s];
            redB[h] += redB[h + s];
        }
        __syncthreads();
    }
    if (h == 0) {
        g_c01[0] = redA[0];
        g_c01[1] = redB[0];
    }
}

__device__ __forceinline__ float tanh_fast(float z) {
    float t;
    asm("tanh.approx.f32 %0, %1;" : "=f"(t) : "f"(z));
    return t;
}

__device__ __forceinline__ void mma_tf32(float* d, float a0, float a1, float a2,
                                         float a3, uint32_t b0, uint32_t b1) {
    asm volatile(
        "mma.sync.aligned.m16n8k8.row.col.f32.tf32.tf32.f32 "
        "{%0,%1,%2,%3}, {%4,%5,%6,%7}, {%8,%9}, {%0,%1,%2,%3};"
        : "+f"(d[0]), "+f"(d[1]), "+f"(d[2]), "+f"(d[3])
        : "r"(__float_as_uint(a0)), "r"(__float_as_uint(a1)),
          "r"(__float_as_uint(a2)), "r"(__float_as_uint(a3)), "r"(b0), "r"(b1));
}

__global__ __launch_bounds__(TPB) void pde_kernel(const float* __restrict__ x,
                                                  const float* __restrict__ b2,
                                                  float* __restrict__ out,
                                                  int N) {
    __shared__ float2 s_ab[HID];          // 8 KB
    __shared__ float s_cc[HID];           // 4 KB
    __shared__ float s_wt[4 * WT_STRIDE]; // 16.5 KB, transposed {w|wa|wb|wbb}

    int tid = threadIdx.x;
    for (int i = tid; i < HID; i += TPB) {
        s_ab[i] = g_ab[i];
        s_cc[i] = g_cc[i];
        float4 wv = g_wv[i];
        s_wt[0 * WT_STRIDE + i] = wv.x;
        s_wt[1 * WT_STRIDE + i] = wv.y;
        s_wt[2 * WT_STRIDE + i] = wv.z;
        s_wt[3 * WT_STRIDE + i] = wv.w;
    }
    __syncthreads();

    int lane = tid & 31;
    int wid = tid >> 5;
    int g = lane >> 2;   // group id = output column n, also row base
    int tig = lane & 3;  // thread-in-group = k sub-col
    int n = g;
    // Octet (j) in which this output column's B entry is nonzero:
    // n=0 (w,t): j=0 ; n=1,2 (wa,wb with tt): j=1 ; n=3 (wbb,t3): j=2
    int jn = (n == 0) ? 0 : (n <= 2) ? 1 : (n == 3) ? 2 : -1;

    int base_pt = blockIdx.x * TPB + wid * 32;

    // Distribute x: lane loads its own point, shuffle to fragment rows.
    float2 myx = reinterpret_cast<const float2*>(x)[base_pt + lane];
    float x0r[4], x1r[4];
#pragma unroll
    for (int i = 0; i < 4; i++) {
        x0r[i] = __shfl_sync(0xffffffffu, myx.x, g + 8 * i);
        x1r[i] = __shfl_sync(0xffffffffu, myx.y, g + 8 * i);
    }

    float acc0[4] = {0.f, 0.f, 0.f, 0.f};  // tile0: rows g, g+8
    float acc1[4] = {0.f, 0.f, 0.f, 0.f};  // tile1: rows g+16, g+24

    float w0 = 0.f, w1 = 0.f;

#pragma unroll 2
    for (int tr = 0; tr < NTRI; tr++) {
        int h0 = tr * 8 + tig;
        int h1 = h0 + 4;
        float2 ab0 = s_ab[h0];
        float2 ab1 = s_ab[h1];
        float cc0 = s_cc[h0];
        float cc1 = s_cc[h1];
        if (n < 4) {
            w0 = s_wt[n * WT_STRIDE + h0];
            w1 = s_wt[n * WT_STRIDE + h1];
        }

        float v[3][4][2];
#pragma unroll
        for (int r = 0; r < 4; r++) {
            float z0 = __fmaf_rn(x1r[r], ab0.y, __fmaf_rn(x0r[r], ab0.x, cc0));
            float t0 = tanh_fast(z0);
            float tt0 = t0 * t0;
            float t30 = __fmaf_rn(-t0, tt0, t0);
            v[0][r][0] = t0;
            v[1][r][0] = tt0;
            v[2][r][0] = t30;
            float z1 = __fmaf_rn(x1r[r], ab1.y, __fmaf_rn(x0r[r], ab1.x, cc1));
            float t1 = tanh_fast(z1);
            float tt1 = t1 * t1;
            float t31 = __fmaf_rn(-t1, tt1, t1);
            v[0][r][1] = t1;
            v[1][r][1] = tt1;
            v[2][r][1] = t31;
        }
#pragma unroll
        for (int j = 0; j < 3; j++) {
            uint32_t b0 = (j == jn) ? __float_as_uint(w0) : 0u;
            uint32_t b1 = (j == jn) ? __float_as_uint(w1) : 0u;
            mma_tf32(acc0, v[j][0][0], v[j][1][0], v[j][0][1], v[j][1][1], b0, b1);
            mma_tf32(acc1, v[j][2][0], v[j][3][0], v[j][2][1], v[j][3][1], b0, b1);
        }
    }

    // Epilogue: thread (g, tig=0) holds cols 0,1 = {out, gA} for rows g(+8,+16,+24);
    // tig=1 holds cols 2,3 = {gB, dx}. Pull gB/dx over with shuffles.
    float sb00 = __shfl_down_sync(0xffffffffu, acc0[0], 1);
    float sb01 = __shfl_down_sync(0xffffffffu, acc0[1], 1);
    float sb02 = __shfl_down_sync(0xffffffffu, acc0[2], 1);
    float sb03 = __shfl_down_sync(0xffffffffu, acc0[3], 1);
    float sb10 = __shfl_down_sync(0xffffffffu, acc1[0], 1);
    float sb11 = __shfl_down_sync(0xffffffffu, acc1[1], 1);
    float sb12 = __shfl_down_sync(0xffffffffu, acc1[2], 1);
    float sb13 = __shfl_down_sync(0xffffffffu, acc1[3], 1);

    if (tig == 0) {
        float C0 = g_c01[0];
        float C1 = g_c01[1];
        float bz = b2[0];

        float ov[4], gA[4], gB[4], dx[4];
        ov[0] = acc0[0]; gA[0] = acc0[1]; gB[0] = sb00; dx[0] = sb01;
        ov[1] = acc0[2]; gA[1] = acc0[3]; gB[1] = sb02; dx[1] = sb03;
        ov[2] = acc1[0]; gA[2] = acc1[1]; gB[2] = sb10; dx[2] = sb11;
        ov[3] = acc1[2]; gA[3] = acc1[3]; gB[3] = sb12; dx[3] = sb13;

#pragma unroll
        for (int r = 0; r < 4; r++) {
            int p = base_pt + g + 8 * r;
            float g0 = C0 - gA[r];
            float g1 = C1 - gB[r];
            float xx1 = x1r[r];
            float pde = __fmaf_rn(0.5f * xx1, xx1, g0);
            pde = __fmaf_rn(0.5f, dx[r], pde);
            pde = __fmaf_rn(0.5f * xx1, g1, pde);
            pde = __fmaf_rn(-0.069444444444444444f * g1, g1, pde);
            out[p] = ov[r] + bz;
            out[N + p] = pde;
        }
    }
}

extern "C" void kernel_launch(void* const* d_in, const int* in_sizes, int n_in,
                              void* d_out, int out_size) {
    const float* x = (const float*)d_in[0];
    const float* W1 = (const float*)d_in[1];
    const float* b1 = (const float*)d_in[2];
    const float* w2 = (const float*)d_in[3];
    const float* b2 = (const float*)d_in[4];
    int N = in_sizes[0] / 2;

    setup_kernel<<<1, HID>>>(W1, b1, w2);
    pde_kernel<<<N / TPB, TPB>>>(x, b2, (float*)d_out, N);
}